// round 10
// baseline (speedup 1.0000x reference)
#include <cuda_runtime.h>
#include <cuda_bf16.h>
#include <math.h>
#include <stdint.h>

// Problem constants
constexpr int S  = 2048;
constexpr int Bb = 2;
constexpr int E  = 1024;
constexpr int H  = 16;
constexpr int HD = 64;
constexpr int M  = S * Bb;   // 4096 rows

// ---------------------------------------------------------------------------
// Scratch (__device__ globals; allocation-free rule)
// ---------------------------------------------------------------------------
__device__ __align__(256) __nv_bfloat16 g_x_hi [M * E],     g_x_lo [M * E];
__device__ __align__(256) __nv_bfloat16 g_wt_hi[E * E],     g_wt_lo[E * E];
__device__ __align__(256) __nv_bfloat16 g_wi_hi[3 * E * E], g_wi_lo[3 * E * E];
__device__ __align__(256) __nv_bfloat16 g_wo_hi[E * E],     g_wo_lo[E * E];
__device__ __align__(256) __nv_bfloat16 g_xt_hi[M * E],     g_xt_lo[M * E];
__device__ __align__(256) __nv_bfloat16 g_qk_hi[(size_t)M * 3 * E];
__device__ __align__(256) __nv_bfloat16 g_qk_lo[(size_t)M * 3 * E];
__device__ __align__(256) __nv_bfloat16 g_oa_hi[M * E],     g_oa_lo[M * E];

// ---------------------------------------------------------------------------
// PTX helpers (baseline PTX only)
// ---------------------------------------------------------------------------
__device__ __forceinline__ uint32_t smem_u32(const void* p) {
    uint32_t a;
    asm("{ .reg .u64 t; cvta.to.shared.u64 t, %1; cvt.u32.u64 %0, t; }"
        : "=r"(a) : "l"(p));
    return a;
}

__device__ __forceinline__ void cp16(uint32_t dst, const void* src) {
    asm volatile("cp.async.cg.shared.global [%0], [%1], 16;"
                 :: "r"(dst), "l"(src) : "memory");
}
#define CP_COMMIT() asm volatile("cp.async.commit_group;" ::: "memory")
#define CP_WAIT(n)  asm volatile("cp.async.wait_group %0;" :: "n"(n) : "memory")

__device__ __forceinline__ void ldsm4(uint32_t* r, uint32_t addr) {
    asm volatile("ldmatrix.sync.aligned.m8n8.x4.shared.b16 {%0,%1,%2,%3}, [%4];"
                 : "=r"(r[0]), "=r"(r[1]), "=r"(r[2]), "=r"(r[3]) : "r"(addr));
}
__device__ __forceinline__ void ldsm4t(uint32_t* r, uint32_t addr) {
    asm volatile("ldmatrix.sync.aligned.m8n8.x4.trans.shared.b16 {%0,%1,%2,%3}, [%4];"
                 : "=r"(r[0]), "=r"(r[1]), "=r"(r[2]), "=r"(r[3]) : "r"(addr));
}

__device__ __forceinline__ void mma16816(float* d, const uint32_t* a,
                                         uint32_t b0, uint32_t b1) {
    asm volatile(
        "mma.sync.aligned.m16n8k16.row.col.f32.bf16.bf16.f32 "
        "{%0,%1,%2,%3}, {%4,%5,%6,%7}, {%8,%9}, {%0,%1,%2,%3};"
        : "+f"(d[0]), "+f"(d[1]), "+f"(d[2]), "+f"(d[3])
        : "r"(a[0]), "r"(a[1]), "r"(a[2]), "r"(a[3]), "r"(b0), "r"(b1));
}

// pack two fp32 -> bf16x2 (lo in lower half)
__device__ __forceinline__ uint32_t packbf(float lo, float hi) {
    uint32_t d;
    asm("cvt.rn.bf16x2.f32 %0, %1, %2;" : "=r"(d) : "f"(hi), "f"(lo));
    return d;
}

__device__ __forceinline__ float ex2f(float x) {
    float y;
    asm("ex2.approx.f32 %0, %1;" : "=f"(y) : "f"(x));
    return y;
}

// ---------------------------------------------------------------------------
// Fused fp32 -> (bf16 hi, bf16 lo) split over all four operands, one launch.
// ---------------------------------------------------------------------------
constexpr int SPL_N0 = 1048576;            // x
constexpr int SPL_N1 = SPL_N0 + 262144;    // + w_tor
constexpr int SPL_N2 = SPL_N1 + 786432;    // + in_w
constexpr int SPL_N3 = SPL_N2 + 262144;    // + out_w  (total)

__global__ void split_all(const float* __restrict__ x, const float* __restrict__ wt,
                          const float* __restrict__ wi, const float* __restrict__ wo,
                          __nv_bfloat16* __restrict__ xh, __nv_bfloat16* __restrict__ xl,
                          __nv_bfloat16* __restrict__ wth, __nv_bfloat16* __restrict__ wtl,
                          __nv_bfloat16* __restrict__ wih, __nv_bfloat16* __restrict__ wil,
                          __nv_bfloat16* __restrict__ woh, __nv_bfloat16* __restrict__ wol)
{
    int i = blockIdx.x * blockDim.x + threadIdx.x;
    if (i >= SPL_N3) return;
    const float* in; __nv_bfloat16 *hi, *lo; int base;
    if (i < SPL_N0)      { in = x;  hi = xh;  lo = xl;  base = 0; }
    else if (i < SPL_N1) { in = wt; hi = wth; lo = wtl; base = SPL_N0; }
    else if (i < SPL_N2) { in = wi; hi = wih; lo = wil; base = SPL_N1; }
    else                 { in = wo; hi = woh; lo = wol; base = SPL_N2; }
    i -= base;
    float4 v = ((const float4*)in)[i];
    __nv_bfloat16 h0 = __float2bfloat16(v.x);
    __nv_bfloat16 h1 = __float2bfloat16(v.y);
    __nv_bfloat16 h2 = __float2bfloat16(v.z);
    __nv_bfloat16 h3 = __float2bfloat16(v.w);
    __nv_bfloat16 l0 = __float2bfloat16(v.x - __bfloat162float(h0));
    __nv_bfloat16 l1 = __float2bfloat16(v.y - __bfloat162float(h1));
    __nv_bfloat16 l2 = __float2bfloat16(v.z - __bfloat162float(h2));
    __nv_bfloat16 l3 = __float2bfloat16(v.w - __bfloat162float(h3));
    ((__nv_bfloat162*)hi)[2 * i]     = __halves2bfloat162(h0, h1);
    ((__nv_bfloat162*)hi)[2 * i + 1] = __halves2bfloat162(h2, h3);
    ((__nv_bfloat162*)lo)[2 * i]     = __halves2bfloat162(l0, l1);
    ((__nv_bfloat162*)lo)[2 * i + 1] = __halves2bfloat162(l2, l3);
}

// ---------------------------------------------------------------------------
// HMMA bf16x3 GEMM, 4-stage cp.async pipeline, BK=16:
//   wait(2) -> sync -> issue stage c+3 -> compute stage c.
// 48B padded rows: phases (0,3,6,1,4,7,2,5) mod 128 -> conflict-free ldmatrix.
// ---------------------------------------------------------------------------
constexpr int RB2     = 48;
constexpr int TILE2   = 128 * RB2;          // 6144
constexpr int STG2    = 4 * TILE2;          // 24576
constexpr int NSTAGE  = 4;
constexpr int GSMEM   = NSTAGE * STG2;      // 98304 -> 2 CTAs/SM

template<int MODE>
__global__ __launch_bounds__(256, 2) void gemm_bf16x3_hmma(
    const __nv_bfloat16* __restrict__ Ahp, const __nv_bfloat16* __restrict__ Alp,
    const __nv_bfloat16* __restrict__ Bhp, const __nv_bfloat16* __restrict__ Blp,
    const float* __restrict__ bias,
    float* __restrict__ Cf,
    __nv_bfloat16* __restrict__ Chi, __nv_bfloat16* __restrict__ Clo,
    int Nn, int Kk)
{
    extern __shared__ char smem[];
    const uint32_t sb = smem_u32(smem);

    const int tid  = threadIdx.x;
    const int wid  = tid >> 5;
    const int lane = tid & 31;
    const int m0 = blockIdx.y * 128;
    const int n0 = blockIdx.x * 128;

    const int lrow  = tid >> 1;           // 0..127
    const int lhalf = (tid & 1) * 16;     // byte offset within 32B data row
    const __nv_bfloat16* sAh = Ahp + (size_t)(m0 + lrow) * Kk + (lhalf >> 1);
    const __nv_bfloat16* sAl = Alp + (size_t)(m0 + lrow) * Kk + (lhalf >> 1);
    const __nv_bfloat16* sBh = Bhp + (size_t)(n0 + lrow) * Kk + (lhalf >> 1);
    const __nv_bfloat16* sBl = Blp + (size_t)(n0 + lrow) * Kk + (lhalf >> 1);
    const uint32_t ldst = sb + lrow * RB2 + lhalf;

    auto load_stage = [&](int st, int k0) {
        uint32_t d = ldst + st * STG2;
        cp16(d,             sAh + k0);
        cp16(d + TILE2,     sAl + k0);
        cp16(d + 2 * TILE2, sBh + k0);
        cp16(d + 3 * TILE2, sBl + k0);
    };

    float acc[2][8][4];
    #pragma unroll
    for (int i = 0; i < 2; i++)
        #pragma unroll
        for (int j = 0; j < 8; j++)
            #pragma unroll
            for (int q = 0; q < 4; q++) acc[i][j][q] = 0.f;

    const int wm = (wid & 3) * 32;
    const int wn = (wid >> 2) * 64;
    const int lr  = lane & 15;
    const int lc  = (lane >> 4) * 16;

    const int NCH = Kk / 16;              // 64 chunks

    load_stage(0, 0);   CP_COMMIT();
    load_stage(1, 16);  CP_COMMIT();
    load_stage(2, 32);  CP_COMMIT();

    for (int c = 0; c < NCH; c++) {
        CP_WAIT(2);
        __syncthreads();
        if (c + 3 < NCH) { load_stage((c + 3) & 3, (c + 3) * 16); CP_COMMIT(); }

        const uint32_t stb = sb + (c & 3) * STG2;
        uint32_t ah[2][4], al[2][4], bb[4][4];

        uint32_t aad = stb + (wm + lr) * RB2 + lc;
        ldsm4(ah[0], aad);
        ldsm4(ah[1], aad + 16 * RB2);

        uint32_t bad = stb + 2 * TILE2 + (wn + lr) * RB2 + lc;
        ldsm4(bb[0], bad);
        ldsm4(bb[1], bad + 16 * RB2);
        ldsm4(bb[2], bad + 32 * RB2);
        ldsm4(bb[3], bad + 48 * RB2);

        #pragma unroll
        for (int mi = 0; mi < 2; mi++)
            #pragma unroll
            for (int nj = 0; nj < 8; nj++)
                mma16816(acc[mi][nj], ah[mi], bb[nj >> 1][nj & 1], bb[nj >> 1][2 + (nj & 1)]);

        uint32_t aal = stb + TILE2 + (wm + lr) * RB2 + lc;
        ldsm4(al[0], aal);
        ldsm4(al[1], aal + 16 * RB2);
        #pragma unroll
        for (int mi = 0; mi < 2; mi++)
            #pragma unroll
            for (int nj = 0; nj < 8; nj++)
                mma16816(acc[mi][nj], al[mi], bb[nj >> 1][nj & 1], bb[nj >> 1][2 + (nj & 1)]);

        uint32_t bbl = stb + 3 * TILE2 + (wn + lr) * RB2 + lc;
        ldsm4(bb[0], bbl);
        ldsm4(bb[1], bbl + 16 * RB2);
        ldsm4(bb[2], bbl + 32 * RB2);
        ldsm4(bb[3], bbl + 48 * RB2);
        #pragma unroll
        for (int mi = 0; mi < 2; mi++)
            #pragma unroll
            for (int nj = 0; nj < 8; nj++)
                mma16816(acc[mi][nj], ah[mi], bb[nj >> 1][nj & 1], bb[nj >> 1][2 + (nj & 1)]);
    }

    const int rbase = m0 + wm + (lane >> 2);
    const int cbase = n0 + wn + (lane & 3) * 2;
    #pragma unroll
    for (int mi = 0; mi < 2; mi++) {
        #pragma unroll
        for (int nj = 0; nj < 8; nj++) {
            const int cc = cbase + nj * 8;
            float2 bv = *(const float2*)&bias[cc];
            const int r0 = rbase + mi * 16;
            float v0 = acc[mi][nj][0] + bv.x;
            float v1 = acc[mi][nj][1] + bv.y;
            float v2 = acc[mi][nj][2] + bv.x;
            float v3 = acc[mi][nj][3] + bv.y;
            if (MODE == 0) {
                *(float2*)&Cf[(size_t)r0 * Nn + cc]       = make_float2(v0, v1);
                *(float2*)&Cf[(size_t)(r0 + 8) * Nn + cc] = make_float2(v2, v3);
            } else {
                __nv_bfloat16 h0 = __float2bfloat16(v0), h1 = __float2bfloat16(v1);
                __nv_bfloat16 h2 = __float2bfloat16(v2), h3 = __float2bfloat16(v3);
                __nv_bfloat16 l0 = __float2bfloat16(v0 - __bfloat162float(h0));
                __nv_bfloat16 l1 = __float2bfloat16(v1 - __bfloat162float(h1));
                __nv_bfloat16 l2 = __float2bfloat16(v2 - __bfloat162float(h2));
                __nv_bfloat16 l3 = __float2bfloat16(v3 - __bfloat162float(h3));
                *(__nv_bfloat162*)&Chi[(size_t)r0 * Nn + cc]       = __halves2bfloat162(h0, h1);
                *(__nv_bfloat162*)&Chi[(size_t)(r0 + 8) * Nn + cc] = __halves2bfloat162(h2, h3);
                *(__nv_bfloat162*)&Clo[(size_t)r0 * Nn + cc]       = __halves2bfloat162(l0, l1);
                *(__nv_bfloat162*)&Clo[(size_t)(r0 + 8) * Nn + cc] = __halves2bfloat162(l2, l3);
            }
        }
    }
}

// ---------------------------------------------------------------------------
// HMMA flash-attention (unchanged from R9: 2-pass QK, 3-pass PV, fixed-max)
// ---------------------------------------------------------------------------
constexpr int ARD    = 144;
constexpr int AQTILE = 128 * ARD;
constexpr int AQH = 0, AQL = AQTILE;
constexpr int ASTG0  = 2 * AQTILE;
constexpr int KTILE  = 64 * ARD;
constexpr int ASTGB  = 3 * KTILE;
constexpr int AKH = 0, AVH = KTILE, AVL = 2 * KTILE;
constexpr int ASMEM  = ASTG0 + 2 * ASTGB;

__global__ __launch_bounds__(256, 2) void attn_toroidal_mma(
    const __nv_bfloat16* __restrict__ qkh, const __nv_bfloat16* __restrict__ qkl,
    __nv_bfloat16* __restrict__ ohi, __nv_bfloat16* __restrict__ olo)
{
    extern __shared__ char smc[];
    const uint32_t sb = smem_u32(smc);
    const int tid = threadIdx.x, wid = tid >> 5, lane = tid & 31;
    const int bh = blockIdx.x, b = bh >> 4, h = bh & 15;
    const int q0 = blockIdx.y * 128;

    const size_t RS = 6144;
    const __nv_bfloat16* qh_p = qkh + (size_t)b * 3 * E + h * HD;
    const __nv_bfloat16* ql_p = qkl + (size_t)b * 3 * E + h * HD;
    const __nv_bfloat16* kh_p = qh_p + E;
    const __nv_bfloat16* vh_p = qh_p + 2 * E;
    const __nv_bfloat16* vl_p = ql_p + 2 * E;

    auto load_q = [&]() {
        #pragma unroll
        for (int i = 0; i < 4; i++) {
            int cid = tid + i * 256;
            int row = cid >> 3, ch = cid & 7;
            uint32_t d = sb + row * ARD + ch * 16;
            cp16(d + AQH, qh_p + (size_t)(q0 + row) * RS + ch * 8);
            cp16(d + AQL, ql_p + (size_t)(q0 + row) * RS + ch * 8);
        }
    };
    auto load_kv = [&](int st, int kt) {
        const __nv_bfloat16* bases[3] = { kh_p, vh_p, vl_p };
        uint32_t stg = sb + ASTG0 + st * ASTGB;
        #pragma unroll
        for (int t = 0; t < 3; t++) {
            #pragma unroll
            for (int i = 0; i < 2; i++) {
                int cid = tid + i * 256;
                int row = cid >> 3, ch = cid & 7;
                cp16(stg + t * KTILE + row * ARD + ch * 16,
                     bases[t] + (size_t)(kt * 64 + row) * RS + ch * 8);
            }
        }
    };

    load_q();
    load_kv(0, 0);
    CP_COMMIT();

    const int lr4 = lane >> 2;
    const int lc2 = (lane & 3) * 2;
    const int rowA = q0 + wid * 16 + lr4;
    const int rowB = rowA + 8;

    float Ov[8][4];
    #pragma unroll
    for (int j = 0; j < 8; j++)
        #pragma unroll
        for (int q = 0; q < 4; q++) Ov[j][q] = 0.f;
    float lA = 0.f, lB = 0.f;

    const uint32_t lrow = lane & 15;
    const uint32_t lcb  = (lane >> 4) * 16;
    const uint32_t qaddr0 = sb + (wid * 16 + lrow) * ARD + lcb;

    CP_WAIT(0);
    __syncthreads();
    uint32_t qh_f[4][4];
    #pragma unroll
    for (int ks = 0; ks < 4; ks++) ldsm4(qh_f[ks], qaddr0 + AQH + ks * 32);
    constexpr int NT = S / 64;
    load_kv(1, 1);
    CP_COMMIT();

    const float C1 = 0.18033688f;
    const float CB = 1.44269504f;

    for (int kt = 0; kt < NT; kt++) {
        if (kt > 0) {
            CP_WAIT(0);
            __syncthreads();
            if (kt + 1 < NT) { load_kv((kt + 1) & 1, kt + 1); CP_COMMIT(); }
        }
        const uint32_t stg = sb + ASTG0 + (kt & 1) * ASTGB;

        float Sv[8][4];
        #pragma unroll
        for (int nj = 0; nj < 8; nj++)
            #pragma unroll
            for (int q = 0; q < 4; q++) Sv[nj][q] = 0.f;

        #pragma unroll
        for (int ks = 0; ks < 4; ks++) {
            uint32_t al[4], kf[4][4];
            ldsm4(al, qaddr0 + AQL + ks * 32);
            uint32_t kaddr = stg + AKH + lrow * ARD + ks * 32 + lcb;
            #pragma unroll
            for (int kb = 0; kb < 4; kb++) ldsm4(kf[kb], kaddr + kb * 16 * ARD);
            #pragma unroll
            for (int nj = 0; nj < 8; nj++) {
                uint32_t b0 = kf[nj >> 1][nj & 1], b1 = kf[nj >> 1][2 + (nj & 1)];
                mma16816(Sv[nj], qh_f[ks], b0, b1);
                mma16816(Sv[nj], al, b0, b1);
            }
        }

        const int wband = (kt * 64 - (q0 + wid * 16)) & (S - 1);
        if (wband <= 16 || wband >= S - 64) {
            const int baseA = kt * 64 + lc2 - rowA + 1;
            const int baseB = baseA - 8;
            #pragma unroll
            for (int nj = 0; nj < 8; nj++) {
                int u0 = (baseA + nj * 8)     & (S - 1);
                int u1 = (baseA + nj * 8 + 1) & (S - 1);
                int u2 = (baseB + nj * 8)     & (S - 1);
                int u3 = (baseB + nj * 8 + 1) & (S - 1);
                Sv[nj][0] = ex2f(Sv[nj][0] * C1 + (u0 <= 2 ? CB : 0.f));
                Sv[nj][1] = ex2f(Sv[nj][1] * C1 + (u1 <= 2 ? CB : 0.f));
                Sv[nj][2] = ex2f(Sv[nj][2] * C1 + (u2 <= 2 ? CB : 0.f));
                Sv[nj][3] = ex2f(Sv[nj][3] * C1 + (u3 <= 2 ? CB : 0.f));
                lA += Sv[nj][0] + Sv[nj][1];
                lB += Sv[nj][2] + Sv[nj][3];
            }
        } else {
            #pragma unroll
            for (int nj = 0; nj < 8; nj++) {
                Sv[nj][0] = ex2f(Sv[nj][0] * C1);
                Sv[nj][1] = ex2f(Sv[nj][1] * C1);
                Sv[nj][2] = ex2f(Sv[nj][2] * C1);
                Sv[nj][3] = ex2f(Sv[nj][3] * C1);
                lA += Sv[nj][0] + Sv[nj][1];
                lB += Sv[nj][2] + Sv[nj][3];
            }
        }

        #pragma unroll
        for (int kb = 0; kb < 4; kb++) {
            uint32_t ph[4], pl[4];
            #pragma unroll
            for (int half = 0; half < 2; half++) {
                const float* c = Sv[2 * kb + half];
                uint32_t p01 = packbf(c[0], c[1]);
                uint32_t p23 = packbf(c[2], c[3]);
                ph[half * 2]     = p01;
                ph[half * 2 + 1] = p23;
                float r0 = c[0] - __uint_as_float(p01 << 16);
                float r1 = c[1] - __uint_as_float(p01 & 0xffff0000u);
                float r2 = c[2] - __uint_as_float(p23 << 16);
                float r3 = c[3] - __uint_as_float(p23 & 0xffff0000u);
                pl[half * 2]     = packbf(r0, r1);
                pl[half * 2 + 1] = packbf(r2, r3);
            }
            uint32_t vaddr = stg + AVH + (kb * 16 + lrow) * ARD + lcb;
            #pragma unroll
            for (int db = 0; db < 4; db++) {
                uint32_t vh4[4], vl4[4];
                ldsm4t(vh4, vaddr + db * 32);
                mma16816(Ov[2 * db],     ph, vh4[0], vh4[1]);
                mma16816(Ov[2 * db + 1], ph, vh4[2], vh4[3]);
                mma16816(Ov[2 * db],     pl, vh4[0], vh4[1]);
                mma16816(Ov[2 * db + 1], pl, vh4[2], vh4[3]);
                ldsm4t(vl4, vaddr + KTILE + db * 32);
                mma16816(Ov[2 * db],     ph, vl4[0], vl4[1]);
                mma16816(Ov[2 * db + 1], ph, vl4[2], vl4[3]);
            }
        }
    }

    lA += __shfl_xor_sync(0xffffffffu, lA, 1);
    lA += __shfl_xor_sync(0xffffffffu, lA, 2);
    lB += __shfl_xor_sync(0xffffffffu, lB, 1);
    lB += __shfl_xor_sync(0xffffffffu, lB, 2);
    const float invA = 1.f / lA, invB = 1.f / lB;
    const size_t oA = ((size_t)rowA * Bb + b) * E + h * HD;
    const size_t oB = ((size_t)rowB * Bb + b) * E + h * HD;
    #pragma unroll
    for (int nj = 0; nj < 8; nj++) {
        const int dc = nj * 8 + lc2;
        float v0 = Ov[nj][0] * invA, v1 = Ov[nj][1] * invA;
        float v2 = Ov[nj][2] * invB, v3 = Ov[nj][3] * invB;
        uint32_t hA = packbf(v0, v1);
        uint32_t hB = packbf(v2, v3);
        float r0 = v0 - __uint_as_float(hA << 16);
        float r1 = v1 - __uint_as_float(hA & 0xffff0000u);
        float r2 = v2 - __uint_as_float(hB << 16);
        float r3 = v3 - __uint_as_float(hB & 0xffff0000u);
        *(uint32_t*)&ohi[oA + dc] = hA;
        *(uint32_t*)&ohi[oB + dc] = hB;
        *(uint32_t*)&olo[oA + dc] = packbf(r0, r1);
        *(uint32_t*)&olo[oB + dc] = packbf(r2, r3);
    }
}

// ---------------------------------------------------------------------------
// Host side
// ---------------------------------------------------------------------------
extern "C" void kernel_launch(void* const* d_in, const int* in_sizes, int n_in,
                              void* d_out, int out_size)
{
    (void)in_sizes; (void)n_in; (void)out_size;
    const float* x     = (const float*)d_in[0];
    const float* w_tor = (const float*)d_in[1];
    const float* b_tor = (const float*)d_in[2];
    const float* in_w  = (const float*)d_in[3];
    const float* in_b  = (const float*)d_in[4];
    const float* out_w = (const float*)d_in[5];
    const float* out_b = (const float*)d_in[6];
    float* out = (float*)d_out;

    __nv_bfloat16 *x_hi, *x_lo, *wt_hi, *wt_lo, *wi_hi, *wi_lo, *wo_hi, *wo_lo;
    __nv_bfloat16 *xt_hi, *xt_lo, *qk_hi, *qk_lo, *oa_hi, *oa_lo;
    cudaGetSymbolAddress((void**)&x_hi,  g_x_hi);  cudaGetSymbolAddress((void**)&x_lo,  g_x_lo);
    cudaGetSymbolAddress((void**)&wt_hi, g_wt_hi); cudaGetSymbolAddress((void**)&wt_lo, g_wt_lo);
    cudaGetSymbolAddress((void**)&wi_hi, g_wi_hi); cudaGetSymbolAddress((void**)&wi_lo, g_wi_lo);
    cudaGetSymbolAddress((void**)&wo_hi, g_wo_hi); cudaGetSymbolAddress((void**)&wo_lo, g_wo_lo);
    cudaGetSymbolAddress((void**)&xt_hi, g_xt_hi); cudaGetSymbolAddress((void**)&xt_lo, g_xt_lo);
    cudaGetSymbolAddress((void**)&qk_hi, g_qk_hi); cudaGetSymbolAddress((void**)&qk_lo, g_qk_lo);
    cudaGetSymbolAddress((void**)&oa_hi, g_oa_hi); cudaGetSymbolAddress((void**)&oa_lo, g_oa_lo);

    cudaFuncSetAttribute(gemm_bf16x3_hmma<0>, cudaFuncAttributeMaxDynamicSharedMemorySize, GSMEM);
    cudaFuncSetAttribute(gemm_bf16x3_hmma<1>, cudaFuncAttributeMaxDynamicSharedMemorySize, GSMEM);
    cudaFuncSetAttribute(attn_toroidal_mma, cudaFuncAttributeMaxDynamicSharedMemorySize, ASMEM);

    split_all<<<(SPL_N3 + 255) / 256, 256>>>(x, w_tor, in_w, out_w,
        x_hi, x_lo, wt_hi, wt_lo, wi_hi, wi_lo, wo_hi, wo_lo);

    // 1. xt = x @ w_tor^T + b_tor  (split bf16 output)
    gemm_bf16x3_hmma<1><<<dim3(E / 128, M / 128), 256, GSMEM>>>(
        x_hi, x_lo, wt_hi, wt_lo, b_tor, nullptr, xt_hi, xt_lo, E, E);
    // 2. qkv = xt @ in_proj_w^T + in_proj_b  (split bf16 output)
    gemm_bf16x3_hmma<1><<<dim3(3 * E / 128, M / 128), 256, GSMEM>>>(
        xt_hi, xt_lo, wi_hi, wi_lo, in_b, nullptr, qk_hi, qk_lo, 3 * E, E);
    // 3. attention (HMMA, 2-pass QK / 3-pass PV, split bf16 output)
    attn_toroidal_mma<<<dim3(Bb * H, S / 128), 256, ASMEM>>>(qk_hi, qk_lo, oa_hi, oa_lo);
    // 4. out = o @ out_w^T + out_b  (fp32 output)
    gemm_bf16x3_hmma<0><<<dim3(E / 128, M / 128), 256, GSMEM>>>(
        oa_hi, oa_lo, wo_hi, wo_lo, out_b, out, nullptr, nullptr, E, E);
}

// round 11
// speedup vs baseline: 1.0206x; 1.0206x over previous
#include <cuda_runtime.h>
#include <cuda_bf16.h>
#include <math.h>
#include <stdint.h>

// Problem constants
constexpr int S  = 2048;
constexpr int Bb = 2;
constexpr int E  = 1024;
constexpr int H  = 16;
constexpr int HD = 64;
constexpr int M  = S * Bb;   // 4096 rows

// ---------------------------------------------------------------------------
// Scratch (__device__ globals; allocation-free rule)
// ---------------------------------------------------------------------------
__device__ __align__(256) __nv_bfloat16 g_x_hi [M * E],      g_x_lo [M * E];
__device__ __align__(256) __nv_bfloat16 g_wi_hi[3 * E * E],  g_wi_lo[3 * E * E];
__device__ __align__(256) __nv_bfloat16 g_wo_hi[E * E],      g_wo_lo[E * E];
__device__ __align__(256) __nv_bfloat16 g_wtt_hi[E * E],     g_wtt_lo[E * E];   // w_tor^T split
__device__ __align__(256) __nv_bfloat16 g_wc_hi[3 * E * E],  g_wc_lo[3 * E * E]; // Wc = in_w @ w_tor
__device__ __align__(256) __nv_bfloat16 g_qk_hi[(size_t)M * 3 * E];
__device__ __align__(256) __nv_bfloat16 g_qk_lo[(size_t)M * 3 * E];
__device__ __align__(256) __nv_bfloat16 g_oa_hi[M * E],      g_oa_lo[M * E];
__device__ float g_bc[3 * E];            // folded qkv bias
__device__ float g_zbias[E];             // static zero-init -> zero bias

// ---------------------------------------------------------------------------
// PTX helpers (baseline PTX only)
// ---------------------------------------------------------------------------
__device__ __forceinline__ uint32_t smem_u32(const void* p) {
    uint32_t a;
    asm("{ .reg .u64 t; cvta.to.shared.u64 t, %1; cvt.u32.u64 %0, t; }"
        : "=r"(a) : "l"(p));
    return a;
}

__device__ __forceinline__ void cp16(uint32_t dst, const void* src) {
    asm volatile("cp.async.cg.shared.global [%0], [%1], 16;"
                 :: "r"(dst), "l"(src) : "memory");
}
#define CP_COMMIT() asm volatile("cp.async.commit_group;" ::: "memory")
#define CP_WAIT(n)  asm volatile("cp.async.wait_group %0;" :: "n"(n) : "memory")

__device__ __forceinline__ void ldsm4(uint32_t* r, uint32_t addr) {
    asm volatile("ldmatrix.sync.aligned.m8n8.x4.shared.b16 {%0,%1,%2,%3}, [%4];"
                 : "=r"(r[0]), "=r"(r[1]), "=r"(r[2]), "=r"(r[3]) : "r"(addr));
}
__device__ __forceinline__ void ldsm4t(uint32_t* r, uint32_t addr) {
    asm volatile("ldmatrix.sync.aligned.m8n8.x4.trans.shared.b16 {%0,%1,%2,%3}, [%4];"
                 : "=r"(r[0]), "=r"(r[1]), "=r"(r[2]), "=r"(r[3]) : "r"(addr));
}

__device__ __forceinline__ void mma16816(float* d, const uint32_t* a,
                                         uint32_t b0, uint32_t b1) {
    asm volatile(
        "mma.sync.aligned.m16n8k16.row.col.f32.bf16.bf16.f32 "
        "{%0,%1,%2,%3}, {%4,%5,%6,%7}, {%8,%9}, {%0,%1,%2,%3};"
        : "+f"(d[0]), "+f"(d[1]), "+f"(d[2]), "+f"(d[3])
        : "r"(a[0]), "r"(a[1]), "r"(a[2]), "r"(a[3]), "r"(b0), "r"(b1));
}

// pack two fp32 -> bf16x2 (lo in lower half)
__device__ __forceinline__ uint32_t packbf(float lo, float hi) {
    uint32_t d;
    asm("cvt.rn.bf16x2.f32 %0, %1, %2;" : "=r"(d) : "f"(hi), "f"(lo));
    return d;
}

__device__ __forceinline__ float ex2f(float x) {
    float y;
    asm("ex2.approx.f32 %0, %1;" : "=f"(y) : "f"(x));
    return y;
}

// ---------------------------------------------------------------------------
// Fused fp32 -> (bf16 hi, bf16 lo) split: x | in_w | out_w (w_tor handled by
// the transpose-split kernel below).
// ---------------------------------------------------------------------------
constexpr int SPL_N0 = 1048576;            // x            (float4 units)
constexpr int SPL_N1 = SPL_N0 + 786432;    // + in_w
constexpr int SPL_N2 = SPL_N1 + 262144;    // + out_w  (total)

__global__ void split_all(const float* __restrict__ x, const float* __restrict__ wi,
                          const float* __restrict__ wo,
                          __nv_bfloat16* __restrict__ xh, __nv_bfloat16* __restrict__ xl,
                          __nv_bfloat16* __restrict__ wih, __nv_bfloat16* __restrict__ wil,
                          __nv_bfloat16* __restrict__ woh, __nv_bfloat16* __restrict__ wol)
{
    int i = blockIdx.x * blockDim.x + threadIdx.x;
    if (i >= SPL_N2) return;
    const float* in; __nv_bfloat16 *hi, *lo; int base;
    if (i < SPL_N0)      { in = x;  hi = xh;  lo = xl;  base = 0; }
    else if (i < SPL_N1) { in = wi; hi = wih; lo = wil; base = SPL_N0; }
    else                 { in = wo; hi = woh; lo = wol; base = SPL_N1; }
    i -= base;
    float4 v = ((const float4*)in)[i];
    __nv_bfloat16 h0 = __float2bfloat16(v.x);
    __nv_bfloat16 h1 = __float2bfloat16(v.y);
    __nv_bfloat16 h2 = __float2bfloat16(v.z);
    __nv_bfloat16 h3 = __float2bfloat16(v.w);
    __nv_bfloat16 l0 = __float2bfloat16(v.x - __bfloat162float(h0));
    __nv_bfloat16 l1 = __float2bfloat16(v.y - __bfloat162float(h1));
    __nv_bfloat16 l2 = __float2bfloat16(v.z - __bfloat162float(h2));
    __nv_bfloat16 l3 = __float2bfloat16(v.w - __bfloat162float(h3));
    ((__nv_bfloat162*)hi)[2 * i]     = __halves2bfloat162(h0, h1);
    ((__nv_bfloat162*)hi)[2 * i + 1] = __halves2bfloat162(h2, h3);
    ((__nv_bfloat162*)lo)[2 * i]     = __halves2bfloat162(l0, l1);
    ((__nv_bfloat162*)lo)[2 * i + 1] = __halves2bfloat162(l2, l3);
}

// ---------------------------------------------------------------------------
// Transposed split of w_tor: wtt[j][k] = w_tor[k][j], as (hi, lo) bf16.
// 32x32 smem tiles; block (32, 8).
// ---------------------------------------------------------------------------
__global__ void transpose_split(const float* __restrict__ in,
                                __nv_bfloat16* __restrict__ th,
                                __nv_bfloat16* __restrict__ tl)
{
    __shared__ float tile[32][33];
    const int bx = blockIdx.x * 32;   // col base of 'in'
    const int by = blockIdx.y * 32;   // row base of 'in'
    const int tx = threadIdx.x, ty = threadIdx.y;
    #pragma unroll
    for (int i = 0; i < 4; i++)
        tile[ty + i * 8][tx] = in[(size_t)(by + ty + i * 8) * E + bx + tx];
    __syncthreads();
    #pragma unroll
    for (int i = 0; i < 4; i++) {
        float v = tile[tx][ty + i * 8];   // = in[by+tx][bx+ty+i*8]
        __nv_bfloat16 h = __float2bfloat16(v);
        __nv_bfloat16 l = __float2bfloat16(v - __bfloat162float(h));
        size_t o = (size_t)(bx + ty + i * 8) * E + by + tx;
        th[o] = h;
        tl[o] = l;
    }
}

// ---------------------------------------------------------------------------
// bc = in_w @ b_tor + in_b  (fp32 exact; one warp per output row)
// ---------------------------------------------------------------------------
__global__ void bias_fold(const float* __restrict__ in_w, const float* __restrict__ b_tor,
                          const float* __restrict__ in_b, float* __restrict__ bc)
{
    const int row  = blockIdx.x * 8 + (threadIdx.x >> 5);
    const int lane = threadIdx.x & 31;
    const float* w = in_w + (size_t)row * E;
    float s = 0.f;
    #pragma unroll 4
    for (int k = lane; k < E; k += 32) s += w[k] * b_tor[k];
    #pragma unroll
    for (int o = 16; o >= 1; o >>= 1) s += __shfl_xor_sync(0xffffffffu, s, o);
    if (lane == 0) bc[row] = s + in_b[row];
}

// ---------------------------------------------------------------------------
// HMMA bf16x3 GEMM — reverted to the proven R9 config:
// BK=32, double buffer, single-sync pipeline, 80B padded rows.
// ---------------------------------------------------------------------------
constexpr int RB      = 80;
constexpr int TILE_B  = 128 * RB;
constexpr int STAGE_B = 4 * TILE_B;
constexpr int GSMEM   = 2 * STAGE_B;

template<int MODE>
__global__ __launch_bounds__(256, 2) void gemm_bf16x3_hmma(
    const __nv_bfloat16* __restrict__ Ahp, const __nv_bfloat16* __restrict__ Alp,
    const __nv_bfloat16* __restrict__ Bhp, const __nv_bfloat16* __restrict__ Blp,
    const float* __restrict__ bias,
    float* __restrict__ Cf,
    __nv_bfloat16* __restrict__ Chi, __nv_bfloat16* __restrict__ Clo,
    int Nn, int Kk)
{
    extern __shared__ char smem[];
    const uint32_t sb = smem_u32(smem);

    const int tid  = threadIdx.x;
    const int wid  = tid >> 5;
    const int lane = tid & 31;
    const int m0 = blockIdx.y * 128;
    const int n0 = blockIdx.x * 128;

    const int lrow = tid >> 1;
    const int lhalf = (tid & 1) * 32;
    const __nv_bfloat16* srcs[4] = {
        Ahp + (size_t)(m0 + lrow) * Kk,
        Alp + (size_t)(m0 + lrow) * Kk,
        Bhp + (size_t)(n0 + lrow) * Kk,
        Blp + (size_t)(n0 + lrow) * Kk };

    auto load_stage = [&](int st, int k0) {
        uint32_t dbase = sb + st * STAGE_B + lrow * RB + lhalf;
        #pragma unroll
        for (int t = 0; t < 4; t++) {
            const __nv_bfloat16* s = srcs[t] + k0 + (lhalf >> 1);
            cp16(dbase + t * TILE_B,      s);
            cp16(dbase + t * TILE_B + 16, s + 8);
        }
    };

    float acc[2][8][4];
    #pragma unroll
    for (int i = 0; i < 2; i++)
        #pragma unroll
        for (int j = 0; j < 8; j++)
            #pragma unroll
            for (int q = 0; q < 4; q++) acc[i][j][q] = 0.f;

    const int wm = (wid & 3) * 32;
    const int wn = (wid >> 2) * 64;
    const int lr  = lane & 15;
    const int lc  = (lane >> 4) * 16;

    const int NCH = Kk / 32;
    load_stage(0, 0);
    CP_COMMIT();

    for (int c = 0; c < NCH; c++) {
        CP_WAIT(0);
        __syncthreads();
        if (c + 1 < NCH) { load_stage((c + 1) & 1, (c + 1) * 32); CP_COMMIT(); }

        const uint32_t stb = sb + (c & 1) * STAGE_B;
        #pragma unroll
        for (int ks = 0; ks < 2; ks++) {
            const uint32_t koff = ks * 32 + lc;
            uint32_t ah[2][4], al[2][4], bb[4][4];

            uint32_t aad = stb + (wm + lr) * RB + koff;
            ldsm4(ah[0], aad);
            ldsm4(ah[1], aad + 16 * RB);

            uint32_t bad = stb + 2 * TILE_B + (wn + lr) * RB + koff;
            ldsm4(bb[0], bad);
            ldsm4(bb[1], bad + 16 * RB);
            ldsm4(bb[2], bad + 32 * RB);
            ldsm4(bb[3], bad + 48 * RB);

            #pragma unroll
            for (int mi = 0; mi < 2; mi++)
                #pragma unroll
                for (int nj = 0; nj < 8; nj++)
                    mma16816(acc[mi][nj], ah[mi], bb[nj >> 1][nj & 1], bb[nj >> 1][2 + (nj & 1)]);

            uint32_t aal = stb + TILE_B + (wm + lr) * RB + koff;
            ldsm4(al[0], aal);
            ldsm4(al[1], aal + 16 * RB);
            #pragma unroll
            for (int mi = 0; mi < 2; mi++)
                #pragma unroll
                for (int nj = 0; nj < 8; nj++)
                    mma16816(acc[mi][nj], al[mi], bb[nj >> 1][nj & 1], bb[nj >> 1][2 + (nj & 1)]);

            uint32_t bbl = stb + 3 * TILE_B + (wn + lr) * RB + koff;
            ldsm4(bb[0], bbl);
            ldsm4(bb[1], bbl + 16 * RB);
            ldsm4(bb[2], bbl + 32 * RB);
            ldsm4(bb[3], bbl + 48 * RB);
            #pragma unroll
            for (int mi = 0; mi < 2; mi++)
                #pragma unroll
                for (int nj = 0; nj < 8; nj++)
                    mma16816(acc[mi][nj], ah[mi], bb[nj >> 1][nj & 1], bb[nj >> 1][2 + (nj & 1)]);
        }
    }

    const int rbase = m0 + wm + (lane >> 2);
    const int cbase = n0 + wn + (lane & 3) * 2;
    #pragma unroll
    for (int mi = 0; mi < 2; mi++) {
        #pragma unroll
        for (int nj = 0; nj < 8; nj++) {
            const int cc = cbase + nj * 8;
            float2 bv = *(const float2*)&bias[cc];
            const int r0 = rbase + mi * 16;
            float v0 = acc[mi][nj][0] + bv.x;
            float v1 = acc[mi][nj][1] + bv.y;
            float v2 = acc[mi][nj][2] + bv.x;
            float v3 = acc[mi][nj][3] + bv.y;
            if (MODE == 0) {
                *(float2*)&Cf[(size_t)r0 * Nn + cc]       = make_float2(v0, v1);
                *(float2*)&Cf[(size_t)(r0 + 8) * Nn + cc] = make_float2(v2, v3);
            } else {
                __nv_bfloat16 h0 = __float2bfloat16(v0), h1 = __float2bfloat16(v1);
                __nv_bfloat16 h2 = __float2bfloat16(v2), h3 = __float2bfloat16(v3);
                __nv_bfloat16 l0 = __float2bfloat16(v0 - __bfloat162float(h0));
                __nv_bfloat16 l1 = __float2bfloat16(v1 - __bfloat162float(h1));
                __nv_bfloat16 l2 = __float2bfloat16(v2 - __bfloat162float(h2));
                __nv_bfloat16 l3 = __float2bfloat16(v3 - __bfloat162float(h3));
                *(__nv_bfloat162*)&Chi[(size_t)r0 * Nn + cc]       = __halves2bfloat162(h0, h1);
                *(__nv_bfloat162*)&Chi[(size_t)(r0 + 8) * Nn + cc] = __halves2bfloat162(h2, h3);
                *(__nv_bfloat162*)&Clo[(size_t)r0 * Nn + cc]       = __halves2bfloat162(l0, l1);
                *(__nv_bfloat162*)&Clo[(size_t)(r0 + 8) * Nn + cc] = __halves2bfloat162(l2, l3);
            }
        }
    }
}

// ---------------------------------------------------------------------------
// HMMA flash-attention (unchanged from R9: 2-pass QK, 3-pass PV, fixed-max)
// ---------------------------------------------------------------------------
constexpr int ARD    = 144;
constexpr int AQTILE = 128 * ARD;
constexpr int AQH = 0, AQL = AQTILE;
constexpr int ASTG0  = 2 * AQTILE;
constexpr int KTILE  = 64 * ARD;
constexpr int ASTGB  = 3 * KTILE;
constexpr int AKH = 0, AVH = KTILE, AVL = 2 * KTILE;
constexpr int ASMEM  = ASTG0 + 2 * ASTGB;

__global__ __launch_bounds__(256, 2) void attn_toroidal_mma(
    const __nv_bfloat16* __restrict__ qkh, const __nv_bfloat16* __restrict__ qkl,
    __nv_bfloat16* __restrict__ ohi, __nv_bfloat16* __restrict__ olo)
{
    extern __shared__ char smc[];
    const uint32_t sb = smem_u32(smc);
    const int tid = threadIdx.x, wid = tid >> 5, lane = tid & 31;
    const int bh = blockIdx.x, b = bh >> 4, h = bh & 15;
    const int q0 = blockIdx.y * 128;

    const size_t RS = 6144;
    const __nv_bfloat16* qh_p = qkh + (size_t)b * 3 * E + h * HD;
    const __nv_bfloat16* ql_p = qkl + (size_t)b * 3 * E + h * HD;
    const __nv_bfloat16* kh_p = qh_p + E;
    const __nv_bfloat16* vh_p = qh_p + 2 * E;
    const __nv_bfloat16* vl_p = ql_p + 2 * E;

    auto load_q = [&]() {
        #pragma unroll
        for (int i = 0; i < 4; i++) {
            int cid = tid + i * 256;
            int row = cid >> 3, ch = cid & 7;
            uint32_t d = sb + row * ARD + ch * 16;
            cp16(d + AQH, qh_p + (size_t)(q0 + row) * RS + ch * 8);
            cp16(d + AQL, ql_p + (size_t)(q0 + row) * RS + ch * 8);
        }
    };
    auto load_kv = [&](int st, int kt) {
        const __nv_bfloat16* bases[3] = { kh_p, vh_p, vl_p };
        uint32_t stg = sb + ASTG0 + st * ASTGB;
        #pragma unroll
        for (int t = 0; t < 3; t++) {
            #pragma unroll
            for (int i = 0; i < 2; i++) {
                int cid = tid + i * 256;
                int row = cid >> 3, ch = cid & 7;
                cp16(stg + t * KTILE + row * ARD + ch * 16,
                     bases[t] + (size_t)(kt * 64 + row) * RS + ch * 8);
            }
        }
    };

    load_q();
    load_kv(0, 0);
    CP_COMMIT();

    const int lr4 = lane >> 2;
    const int lc2 = (lane & 3) * 2;
    const int rowA = q0 + wid * 16 + lr4;
    const int rowB = rowA + 8;

    float Ov[8][4];
    #pragma unroll
    for (int j = 0; j < 8; j++)
        #pragma unroll
        for (int q = 0; q < 4; q++) Ov[j][q] = 0.f;
    float lA = 0.f, lB = 0.f;

    const uint32_t lrow = lane & 15;
    const uint32_t lcb  = (lane >> 4) * 16;
    const uint32_t qaddr0 = sb + (wid * 16 + lrow) * ARD + lcb;

    CP_WAIT(0);
    __syncthreads();
    uint32_t qh_f[4][4];
    #pragma unroll
    for (int ks = 0; ks < 4; ks++) ldsm4(qh_f[ks], qaddr0 + AQH + ks * 32);
    constexpr int NT = S / 64;
    load_kv(1, 1);
    CP_COMMIT();

    const float C1 = 0.18033688f;
    const float CB = 1.44269504f;

    for (int kt = 0; kt < NT; kt++) {
        if (kt > 0) {
            CP_WAIT(0);
            __syncthreads();
            if (kt + 1 < NT) { load_kv((kt + 1) & 1, kt + 1); CP_COMMIT(); }
        }
        const uint32_t stg = sb + ASTG0 + (kt & 1) * ASTGB;

        float Sv[8][4];
        #pragma unroll
        for (int nj = 0; nj < 8; nj++)
            #pragma unroll
            for (int q = 0; q < 4; q++) Sv[nj][q] = 0.f;

        #pragma unroll
        for (int ks = 0; ks < 4; ks++) {
            uint32_t al[4], kf[4][4];
            ldsm4(al, qaddr0 + AQL + ks * 32);
            uint32_t kaddr = stg + AKH + lrow * ARD + ks * 32 + lcb;
            #pragma unroll
            for (int kb = 0; kb < 4; kb++) ldsm4(kf[kb], kaddr + kb * 16 * ARD);
            #pragma unroll
            for (int nj = 0; nj < 8; nj++) {
                uint32_t b0 = kf[nj >> 1][nj & 1], b1 = kf[nj >> 1][2 + (nj & 1)];
                mma16816(Sv[nj], qh_f[ks], b0, b1);
                mma16816(Sv[nj], al, b0, b1);
            }
        }

        const int wband = (kt * 64 - (q0 + wid * 16)) & (S - 1);
        if (wband <= 16 || wband >= S - 64) {
            const int baseA = kt * 64 + lc2 - rowA + 1;
            const int baseB = baseA - 8;
            #pragma unroll
            for (int nj = 0; nj < 8; nj++) {
                int u0 = (baseA + nj * 8)     & (S - 1);
                int u1 = (baseA + nj * 8 + 1) & (S - 1);
                int u2 = (baseB + nj * 8)     & (S - 1);
                int u3 = (baseB + nj * 8 + 1) & (S - 1);
                Sv[nj][0] = ex2f(Sv[nj][0] * C1 + (u0 <= 2 ? CB : 0.f));
                Sv[nj][1] = ex2f(Sv[nj][1] * C1 + (u1 <= 2 ? CB : 0.f));
                Sv[nj][2] = ex2f(Sv[nj][2] * C1 + (u2 <= 2 ? CB : 0.f));
                Sv[nj][3] = ex2f(Sv[nj][3] * C1 + (u3 <= 2 ? CB : 0.f));
                lA += Sv[nj][0] + Sv[nj][1];
                lB += Sv[nj][2] + Sv[nj][3];
            }
        } else {
            #pragma unroll
            for (int nj = 0; nj < 8; nj++) {
                Sv[nj][0] = ex2f(Sv[nj][0] * C1);
                Sv[nj][1] = ex2f(Sv[nj][1] * C1);
                Sv[nj][2] = ex2f(Sv[nj][2] * C1);
                Sv[nj][3] = ex2f(Sv[nj][3] * C1);
                lA += Sv[nj][0] + Sv[nj][1];
                lB += Sv[nj][2] + Sv[nj][3];
            }
        }

        #pragma unroll
        for (int kb = 0; kb < 4; kb++) {
            uint32_t ph[4], pl[4];
            #pragma unroll
            for (int half = 0; half < 2; half++) {
                const float* c = Sv[2 * kb + half];
                uint32_t p01 = packbf(c[0], c[1]);
                uint32_t p23 = packbf(c[2], c[3]);
                ph[half * 2]     = p01;
                ph[half * 2 + 1] = p23;
                float r0 = c[0] - __uint_as_float(p01 << 16);
                float r1 = c[1] - __uint_as_float(p01 & 0xffff0000u);
                float r2 = c[2] - __uint_as_float(p23 << 16);
                float r3 = c[3] - __uint_as_float(p23 & 0xffff0000u);
                pl[half * 2]     = packbf(r0, r1);
                pl[half * 2 + 1] = packbf(r2, r3);
            }
            uint32_t vaddr = stg + AVH + (kb * 16 + lrow) * ARD + lcb;
            #pragma unroll
            for (int db = 0; db < 4; db++) {
                uint32_t vh4[4], vl4[4];
                ldsm4t(vh4, vaddr + db * 32);
                mma16816(Ov[2 * db],     ph, vh4[0], vh4[1]);
                mma16816(Ov[2 * db + 1], ph, vh4[2], vh4[3]);
                mma16816(Ov[2 * db],     pl, vh4[0], vh4[1]);
                mma16816(Ov[2 * db + 1], pl, vh4[2], vh4[3]);
                ldsm4t(vl4, vaddr + KTILE + db * 32);
                mma16816(Ov[2 * db],     ph, vl4[0], vl4[1]);
                mma16816(Ov[2 * db + 1], ph, vl4[2], vl4[3]);
            }
        }
    }

    lA += __shfl_xor_sync(0xffffffffu, lA, 1);
    lA += __shfl_xor_sync(0xffffffffu, lA, 2);
    lB += __shfl_xor_sync(0xffffffffu, lB, 1);
    lB += __shfl_xor_sync(0xffffffffu, lB, 2);
    const float invA = 1.f / lA, invB = 1.f / lB;
    const size_t oA = ((size_t)rowA * Bb + b) * E + h * HD;
    const size_t oB = ((size_t)rowB * Bb + b) * E + h * HD;
    #pragma unroll
    for (int nj = 0; nj < 8; nj++) {
        const int dc = nj * 8 + lc2;
        float v0 = Ov[nj][0] * invA, v1 = Ov[nj][1] * invA;
        float v2 = Ov[nj][2] * invB, v3 = Ov[nj][3] * invB;
        uint32_t hA = packbf(v0, v1);
        uint32_t hB = packbf(v2, v3);
        float r0 = v0 - __uint_as_float(hA << 16);
        float r1 = v1 - __uint_as_float(hA & 0xffff0000u);
        float r2 = v2 - __uint_as_float(hB << 16);
        float r3 = v3 - __uint_as_float(hB & 0xffff0000u);
        *(uint32_t*)&ohi[oA + dc] = hA;
        *(uint32_t*)&ohi[oB + dc] = hB;
        *(uint32_t*)&olo[oA + dc] = packbf(r0, r1);
        *(uint32_t*)&olo[oB + dc] = packbf(r2, r3);
    }
}

// ---------------------------------------------------------------------------
// Host side
// ---------------------------------------------------------------------------
extern "C" void kernel_launch(void* const* d_in, const int* in_sizes, int n_in,
                              void* d_out, int out_size)
{
    (void)in_sizes; (void)n_in; (void)out_size;
    const float* x     = (const float*)d_in[0];
    const float* w_tor = (const float*)d_in[1];
    const float* b_tor = (const float*)d_in[2];
    const float* in_w  = (const float*)d_in[3];
    const float* in_b  = (const float*)d_in[4];
    const float* out_w = (const float*)d_in[5];
    const float* out_b = (const float*)d_in[6];
    float* out = (float*)d_out;

    __nv_bfloat16 *x_hi, *x_lo, *wi_hi, *wi_lo, *wo_hi, *wo_lo;
    __nv_bfloat16 *wtt_hi, *wtt_lo, *wc_hi, *wc_lo, *qk_hi, *qk_lo, *oa_hi, *oa_lo;
    float *bc, *zb;
    cudaGetSymbolAddress((void**)&x_hi,   g_x_hi);   cudaGetSymbolAddress((void**)&x_lo,   g_x_lo);
    cudaGetSymbolAddress((void**)&wi_hi,  g_wi_hi);  cudaGetSymbolAddress((void**)&wi_lo,  g_wi_lo);
    cudaGetSymbolAddress((void**)&wo_hi,  g_wo_hi);  cudaGetSymbolAddress((void**)&wo_lo,  g_wo_lo);
    cudaGetSymbolAddress((void**)&wtt_hi, g_wtt_hi); cudaGetSymbolAddress((void**)&wtt_lo, g_wtt_lo);
    cudaGetSymbolAddress((void**)&wc_hi,  g_wc_hi);  cudaGetSymbolAddress((void**)&wc_lo,  g_wc_lo);
    cudaGetSymbolAddress((void**)&qk_hi,  g_qk_hi);  cudaGetSymbolAddress((void**)&qk_lo,  g_qk_lo);
    cudaGetSymbolAddress((void**)&oa_hi,  g_oa_hi);  cudaGetSymbolAddress((void**)&oa_lo,  g_oa_lo);
    cudaGetSymbolAddress((void**)&bc,     g_bc);
    cudaGetSymbolAddress((void**)&zb,     g_zbias);

    cudaFuncSetAttribute(gemm_bf16x3_hmma<0>, cudaFuncAttributeMaxDynamicSharedMemorySize, GSMEM);
    cudaFuncSetAttribute(gemm_bf16x3_hmma<1>, cudaFuncAttributeMaxDynamicSharedMemorySize, GSMEM);
    cudaFuncSetAttribute(attn_toroidal_mma, cudaFuncAttributeMaxDynamicSharedMemorySize, ASMEM);

    // Operand splits
    split_all<<<(SPL_N2 + 255) / 256, 256>>>(x, in_w, out_w,
        x_hi, x_lo, wi_hi, wi_lo, wo_hi, wo_lo);
    transpose_split<<<dim3(E / 32, E / 32), dim3(32, 8)>>>(w_tor, wtt_hi, wtt_lo);
    bias_fold<<<3 * E / 8, 256>>>(in_w, b_tor, in_b, bc);

    // 1. Wc = in_w @ w_tor  (split bf16 output; zero bias)
    gemm_bf16x3_hmma<1><<<dim3(E / 128, 3 * E / 128), 256, GSMEM>>>(
        wi_hi, wi_lo, wtt_hi, wtt_lo, zb, nullptr, wc_hi, wc_lo, E, E);
    // 2. qkv = x @ Wc^T + bc  (split bf16 output) — GEMM1 fused away
    gemm_bf16x3_hmma<1><<<dim3(3 * E / 128, M / 128), 256, GSMEM>>>(
        x_hi, x_lo, wc_hi, wc_lo, bc, nullptr, qk_hi, qk_lo, 3 * E, E);
    // 3. attention (HMMA, 2-pass QK / 3-pass PV, split bf16 output)
    attn_toroidal_mma<<<dim3(Bb * H, S / 128), 256, ASMEM>>>(qk_hi, qk_lo, oa_hi, oa_lo);
    // 4. out = o @ out_w^T + out_b  (fp32 output)
    gemm_bf16x3_hmma<0><<<dim3(E / 128, M / 128), 256, GSMEM>>>(
        oa_hi, oa_lo, wo_hi, wo_lo, out_b, out, nullptr, nullptr, E, E);
}